// round 7
// baseline (speedup 1.0000x reference)
#include <cuda_runtime.h>

#define Bb 16
#define Nn 512
#define Tt 24
#define Dd 64
#define Ee 64
#define Hh 64
#define ESTR 132   // transposed-buffer row stride (128 + 4 pad)

// E2 scratch, k-major [B,T,E,N]
__device__ float g_e2t[Bb * Tt * Ee * Nn];

typedef unsigned long long ull;

// ---------- helpers ----------
__device__ __forceinline__ ull dup2(float a) {
    ull r;
    asm("mov.b64 %0, {%1, %1};" : "=l"(r) : "f"(a));
    return r;
}
__device__ __forceinline__ void fma2(ull& c, ull a, ull b) {
    asm("fma.rn.f32x2 %0, %1, %2, %0;" : "+l"(c) : "l"(a), "l"(b));
}
__device__ __forceinline__ float2 unpk(ull v) {
    float2 r;
    asm("mov.b64 {%0, %1}, %2;" : "=f"(r.x), "=f"(r.y) : "l"(v));
    return r;
}
__device__ __forceinline__ void cp16(float* s, const float* g) {
    unsigned int sa = (unsigned int)__cvta_generic_to_shared(s);
    asm volatile("cp.async.cg.shared.global [%0], [%1], 16;" ::"r"(sa), "l"(g));
}
__device__ __forceinline__ void cp_commit() { asm volatile("cp.async.commit_group;"); }
template <int N>
__device__ __forceinline__ void cp_wait() {
    asm volatile("cp.async.wait_group %0;" ::"n"(N));
}

// 16 fma2: acc[p][v] += a-pair p * dup(b col v); pairs cover rows 2p,2p+1
__device__ __forceinline__ void mma_pairs(ull (*acc)[4], const float* a_t, int astride,
                                          const float* bm, int k, int r0, int c0) {
    ulonglong2 alo = *(const ulonglong2*)&a_t[k * astride + r0];
    ulonglong2 ahi = *(const ulonglong2*)&a_t[k * astride + r0 + 4];
    float4 bq = *(const float4*)&bm[k * 64 + c0];
    ull b0 = dup2(bq.x), b1 = dup2(bq.y), b2 = dup2(bq.z), b3 = dup2(bq.w);
    fma2(acc[0][0], alo.x, b0); fma2(acc[0][1], alo.x, b1);
    fma2(acc[0][2], alo.x, b2); fma2(acc[0][3], alo.x, b3);
    fma2(acc[1][0], alo.y, b0); fma2(acc[1][1], alo.y, b1);
    fma2(acc[1][2], alo.y, b2); fma2(acc[1][3], alo.y, b3);
    fma2(acc[2][0], ahi.x, b0); fma2(acc[2][1], ahi.x, b1);
    fma2(acc[2][2], ahi.x, b2); fma2(acc[2][3], ahi.x, b3);
    fma2(acc[3][0], ahi.y, b0); fma2(acc[3][1], ahi.y, b1);
    fma2(acc[3][2], ahi.y, b2); fma2(acc[3][3], ahi.y, b3);
}

// unpack pair-accs acc[4][4] -> pv[8][4] (row-major scalars)
__device__ __forceinline__ void unpack_pairs(const ull (*acc)[4], float (*pv)[4]) {
#pragma unroll
    for (int p = 0; p < 4; p++)
#pragma unroll
        for (int v = 0; v < 4; v++) {
            float2 f = unpk(acc[p][v]);
            pv[2 * p][v] = f.x;
            pv[2 * p + 1][v] = f.y;
        }
}

// unpack col-pair accs acc[8][2] (8 rows x 4 cols) -> pv[8][4]
__device__ __forceinline__ void unpack84(const ull (*acc)[2], float (*pv)[4]) {
#pragma unroll
    for (int u = 0; u < 8; u++) {
        float2 p0 = unpk(acc[u][0]), p1 = unpk(acc[u][1]);
        pv[u][0] = p0.x; pv[u][1] = p0.y; pv[u][2] = p1.x; pv[u][3] = p1.y;
    }
}

// store pv[8][4] transposed: base[(c0+v)*stride + r0 + {0,4}]
__device__ __forceinline__ void store_t(float* base, int c0, int r0,
                                        const float (*pv)[4], int stride) {
#pragma unroll
    for (int v = 0; v < 4; v++) {
        *(float4*)&base[(c0 + v) * stride + r0] =
            make_float4(pv[0][v], pv[1][v], pv[2][v], pv[3][v]);
        *(float4*)&base[(c0 + v) * stride + r0 + 4] =
            make_float4(pv[4][v], pv[5][v], pv[6][v], pv[7][v]);
    }
}

// ============================================================================
// Kernel P: E2^T = (x@W2+b2)^T stored k-major [B,T,E,N].
// grid = B*T*8 (one 64-row n-tile per block), 128 threads, 8x4 thread tile.
// ============================================================================
__global__ void __launch_bounds__(128, 4)
gcn_proj(const float* __restrict__ x, const float* __restrict__ W2,
         const float* __restrict__ b2) {
    extern __shared__ float sm[];
    float* xb = sm;          // 4096  x tile [n][d]
    float* Ws = sm + 4096;   // 4096  W2 [d][e]
    float* bs = sm + 8192;   // 64

    const int tid = threadIdx.x;
    const int blk = blockIdx.x;
    const int nt = blk & 7, bt = blk >> 3;
    const int t = bt % Tt, b = bt / Tt;
    const int n0 = nt * 64;
    const float* xg = x + ((size_t)(b * Nn + n0) * Tt + t) * Dd;

#pragma unroll
    for (int i = 0; i < 8; i++) {
        int ch = tid + 128 * i, row = ch >> 4, col = (ch & 15) * 4;
        cp16(&xb[row * 64 + col], &xg[(size_t)row * (Tt * Dd) + col]);
        cp16(&Ws[ch * 4], &W2[ch * 4]);
    }
    if (tid < 16) cp16(&bs[tid * 4], &b2[tid * 4]);
    cp_commit();
    cp_wait<0>();
    __syncthreads();

    const int r0 = (tid >> 4) * 8, c0 = (tid & 15) * 4;
    ull acc[8][2];
    {
        ulonglong2 bb = *(const ulonglong2*)&bs[c0];
#pragma unroll
        for (int u = 0; u < 8; u++) { acc[u][0] = bb.x; acc[u][1] = bb.y; }
    }
#pragma unroll 8
    for (int d = 0; d < 64; d++) {
        ulonglong2 wv = *(const ulonglong2*)&Ws[d * 64 + c0];
#pragma unroll
        for (int u = 0; u < 8; u++) {
            ull ad = dup2(xb[(r0 + u) * 64 + d]);
            fma2(acc[u][0], ad, wv.x);
            fma2(acc[u][1], ad, wv.y);
        }
    }
    float pv[8][4];
    unpack84(acc, pv);
    float* gout = g_e2t + (size_t)(b * Tt + t) * Ee * Nn + n0;
#pragma unroll
    for (int v = 0; v < 4; v++) {
        *(float4*)&gout[(size_t)(c0 + v) * Nn + r0] =
            make_float4(pv[0][v], pv[1][v], pv[2][v], pv[3][v]);
        *(float4*)&gout[(size_t)(c0 + v) * Nn + r0 + 4] =
            make_float4(pv[4][v], pv[5][v], pv[6][v], pv[7][v]);
    }
}

// ============================================================================
// Kernel M: per (b,t,i-tile of 128): E1=x_i@W1+b1; stream 8 j-tiles:
//   S=E1 E2^T, P=exp(relu(S)), H += P X; out = relu((H/rs) W + b)
// grid = B*T*4, 256 threads (8 warps = 4x2 over 128x64), 2 CTAs/SM.
// ============================================================================
__global__ void __launch_bounds__(256, 2)
gcn_main(const float* __restrict__ x, const float* __restrict__ W1,
         const float* __restrict__ b1, const float* __restrict__ W,
         const float* __restrict__ bias, float* __restrict__ out) {
    extern __shared__ float sm[];
    float* e1s   = sm;           // 8448  E1^T [e][i] stride 132
    float* Pt    = sm + 8448;    // 8448  P^T/H^T [j|d][i] stride 132 (also W1 staging)
    float* eb    = sm + 16896;   // 4096  e2 tile [e][j] (also x_i lo staging, W in ph4)
    float* xb    = sm + 20992;   // 4096  x tile [j][d]  (also x_i hi staging)
    float* bs1   = sm + 25088;   // 64
    float* bsO   = sm + 25152;   // 64
    float* rpart = sm + 25216;   // 256  row-sum partials [warpC][row 0..127]
                                 // total 25472 floats = 101,888 B

    const int tid = threadIdx.x;
    const int blk = blockIdx.x;
    const int it = blk & 3, bt = blk >> 2;
    const int t = bt % Tt, b = bt / Tt;
    const int i0 = it * 128;

    const float* e2g = g_e2t + (size_t)(b * Tt + t) * Ee * Nn;
    const float* xg = x + ((size_t)b * Nn * Tt + t) * Dd;

    const int warp = tid >> 5, lane = tid & 31;
    const int wC = warp & 1;
    const int r0 = (warp >> 1) * 32 + (lane >> 3) * 8;   // 0..120
    const int c0 = wC * 32 + (lane & 7) * 4;             // 0..60

    // ---- prologue: x_i (128 rows) -> eb(lo)/xb(hi), W1 -> Pt, biases ----
#pragma unroll
    for (int i = 0; i < 8; i++) {
        int ch = tid + 256 * i, row = ch >> 4, col = (ch & 15) * 4;
        float* dst = (row < 64) ? &eb[row * 64 + col] : &xb[(row - 64) * 64 + col];
        cp16(dst, &xg[(size_t)(i0 + row) * (Tt * Dd) + col]);
    }
#pragma unroll
    for (int i = 0; i < 4; i++) {
        int ch = tid + 256 * i;
        cp16(&Pt[ch * 4], &W1[ch * 4]);
    }
    if (tid < 16) cp16(&bs1[tid * 4], &b1[tid * 4]);
    else if (tid < 32) cp16(&bsO[(tid - 16) * 4], &bias[(tid - 16) * 4]);
    cp_commit();
    cp_wait<0>();
    __syncthreads();

    // ---- GEMM0: E1 = x_i @ W1 + b1 -> e1s transposed (dup-a style) ----
    {
        const int r0g = (tid >> 4) * 8;        // 0..120
        const int c0g = (tid & 15) * 4;        // 0..60
        const float* xsrc = (r0g < 64) ? &eb[r0g * 64] : &xb[(r0g - 64) * 64];
        ull a0[8][2];
        ulonglong2 bb = *(const ulonglong2*)&bs1[c0g];
#pragma unroll
        for (int u = 0; u < 8; u++) { a0[u][0] = bb.x; a0[u][1] = bb.y; }
#pragma unroll 8
        for (int d = 0; d < 64; d++) {
            ulonglong2 wv = *(const ulonglong2*)&Pt[d * 64 + c0g];
#pragma unroll
            for (int u = 0; u < 8; u++) {
                ull ad = dup2(xsrc[u * 64 + d]);
                fma2(a0[u][0], ad, wv.x);
                fma2(a0[u][1], ad, wv.y);
            }
        }
        float pv[8][4];
        unpack84(a0, pv);
        store_t(e1s, c0g, r0g, pv, ESTR);
    }
    __syncthreads();  // e1s visible; eb/xb/Pt reads done -> buffers free

    // kick off pipeline: e2(0) then x(0) as separate groups
#pragma unroll
    for (int i = 0; i < 4; i++) {
        int ch = tid + 256 * i, row = ch >> 4, col = (ch & 15) * 4;
        cp16(&eb[row * 64 + col], &e2g[row * Nn + col]);
    }
    cp_commit();
#pragma unroll
    for (int i = 0; i < 4; i++) {
        int ch = tid + 256 * i, row = ch >> 4, col = (ch & 15) * 4;
        cp16(&xb[row * 64 + col], &xg[(size_t)row * (Tt * Dd) + col]);
    }
    cp_commit();

    float rsp[8] = {0, 0, 0, 0, 0, 0, 0, 0};
    ull acc3[4][4];
#pragma unroll
    for (int p = 0; p < 4; p++)
#pragma unroll
        for (int v = 0; v < 4; v++) acc3[p][v] = 0ull;

    for (int jt = 0; jt < 8; jt++) {
        cp_wait<1>();  // e2(jt) ready
        __syncthreads();

        // ---- GEMM1: S-tile = E1 E2^T (pair-packed rows) ----
        ull acc[4][4];
#pragma unroll
        for (int p = 0; p < 4; p++)
#pragma unroll
            for (int v = 0; v < 4; v++) acc[p][v] = 0ull;
#pragma unroll 8
        for (int e = 0; e < 64; e++) mma_pairs(acc, e1s, ESTR, eb, e, r0, c0);

        // ---- exp(relu) max-free, partial row sums, P^T store ----
        float pv[8][4];
        unpack_pairs(acc, pv);
#pragma unroll
        for (int u = 0; u < 8; u++) {
#pragma unroll
            for (int v = 0; v < 4; v++)
                pv[u][v] = __expf(fminf(fmaxf(pv[u][v], 0.f), 80.f));
            rsp[u] += (pv[u][0] + pv[u][1]) + (pv[u][2] + pv[u][3]);
        }
        store_t(Pt, c0, r0, pv, ESTR);
        __syncthreads();  // Pt complete; eb free

        // prefetch next e2 (or W on last iter) into eb
        if (jt < 7) {
            const float* src = e2g + (jt + 1) * 64;
#pragma unroll
            for (int i = 0; i < 4; i++) {
                int ch = tid + 256 * i, row = ch >> 4, col = (ch & 15) * 4;
                cp16(&eb[row * 64 + col], &src[row * Nn + col]);
            }
        } else {
#pragma unroll
            for (int i = 0; i < 4; i++) {
                int ch = tid + 256 * i;
                cp16(&eb[ch * 4], &W[ch * 4]);
            }
        }
        cp_commit();
        cp_wait<1>();  // x(jt) ready
        __syncthreads();

        // ---- GEMM2: H += P X ----
#pragma unroll 8
        for (int j = 0; j < 64; j++) mma_pairs(acc3, Pt, ESTR, xb, j, r0, c0);
        __syncthreads();  // xb free

        if (jt < 7) {
            const float* src = xg + (size_t)(jt + 1) * 64 * (Tt * Dd);
#pragma unroll
            for (int i = 0; i < 4; i++) {
                int ch = tid + 256 * i, row = ch >> 4, col = (ch & 15) * 4;
                cp16(&xb[row * 64 + col], &src[(size_t)row * (Tt * Dd) + col]);
            }
            cp_commit();
        }
    }

    // ---- finalize row sums: 8-lane butterfly, then cross-warpC combine ----
#pragma unroll
    for (int u = 0; u < 8; u++) {
#pragma unroll
        for (int o = 1; o < 8; o <<= 1)
            rsp[u] += __shfl_xor_sync(0xffffffffu, rsp[u], o);
    }
    if ((lane & 7) == 0) {
#pragma unroll
        for (int u = 0; u < 8; u++) rpart[wC * 128 + r0 + u] = rsp[u];
    }
    __syncthreads();

    // ---- H normalized -> Pt transposed (H^T [d][i]) ----
    {
        float hv[8][4];
        unpack_pairs(acc3, hv);
#pragma unroll
        for (int u = 0; u < 8; u++) {
            float inv = 1.f / (rpart[r0 + u] + rpart[128 + r0 + u]);
#pragma unroll
            for (int v = 0; v < 4; v++) hv[u][v] *= inv;
        }
        store_t(Pt, c0, r0, hv, ESTR);
    }
    cp_wait<0>();  // W in eb
    __syncthreads();

    // ---- GEMM3: out = relu(H W + b) ----
    ull a4[4][4];
    {
#pragma unroll
        for (int v = 0; v < 4; v++) {
            ull bv = dup2(bsO[c0 + v]);
#pragma unroll
            for (int p = 0; p < 4; p++) a4[p][v] = bv;
        }
    }
#pragma unroll 8
    for (int d = 0; d < 64; d++) mma_pairs(a4, Pt, ESTR, eb, d, r0, c0);

    float ov[8][4];
    unpack_pairs(a4, ov);
#pragma unroll
    for (int u = 0; u < 8; u++) {
        float4 o = make_float4(fmaxf(ov[u][0], 0.f), fmaxf(ov[u][1], 0.f),
                               fmaxf(ov[u][2], 0.f), fmaxf(ov[u][3], 0.f));
        *(float4*)&out[((size_t)(b * Nn + i0 + r0 + u) * Tt + t) * Hh + c0] = o;
    }
}

// ============================================================================
extern "C" void kernel_launch(void* const* d_in, const int* in_sizes, int n_in,
                              void* d_out, int out_size) {
    const float* x  = (const float*)d_in[0];
    const float* W1 = (const float*)d_in[1];
    const float* b1 = (const float*)d_in[2];
    const float* W2 = (const float*)d_in[3];
    const float* b2 = (const float*)d_in[4];
    const float* W  = (const float*)d_in[5];
    const float* bias = (const float*)d_in[6];
    float* out = (float*)d_out;

    const int smemP = 8256 * 4;    // 33,024 B
    const int smemM = 25472 * 4;   // 101,888 B
    cudaFuncSetAttribute(gcn_proj, cudaFuncAttributeMaxDynamicSharedMemorySize, smemP);
    cudaFuncSetAttribute(gcn_main, cudaFuncAttributeMaxDynamicSharedMemorySize, smemM);

    gcn_proj<<<Bb * Tt * 8, 128, smemP>>>(x, W2, b2);
    gcn_main<<<Bb * Tt * 4, 256, smemM>>>(x, W1, b1, W, bias, out);
}